// round 14
// baseline (speedup 1.0000x reference)
#include <cuda_runtime.h>
#include <cuda_fp16.h>
#include <cstdint>
#include <float.h>

#define NB   8
#define SEQL 1024
#define NH   16
#define HD   64
#define EMB  1024

// ---------------------------------------------------------------------------
// Device scratch (allocation-free rule)
// ---------------------------------------------------------------------------
__device__ __half g_q [NB*NH*SEQL*HD];     // projected Q (fp16, pre-scaled by XSCALE)
__device__ __half g_k [NB*NH*SEQL*HD];     // projected K (fp16)
__device__ __half g_v [NB*NH*SEQL*HD];     // projected V (fp16)
__device__ __half g_ao[NB*SEQL*EMB];       // attention out (fp16) [n][l][e]
__device__ __half g_wo[EMB*EMB];           // Wo fp16
__device__ unsigned g_mb[NB*SEQL*SEQL/32]; // packed mask bits

// log2 domain: softmax(z/32) = exp2(z * C) / sum, C = log2(e)/32, folded into Wq.
#define XSCALE 0.0450842139f          /* 0.03125 * log2(e) */

// ---------------------------------------------------------------------------
// helpers
// ---------------------------------------------------------------------------
__device__ __forceinline__ uint32_t smem_u32(const void* p) {
    uint32_t a;
    asm("{ .reg .u64 t; cvta.to.shared.u64 t, %1; cvt.u32.u64 %0, t; }"
        : "=r"(a) : "l"(p));
    return a;
}

#define SWZ(o) ((o) ^ ((((uint32_t)(o)) >> 3) & 0x70u))

__device__ __forceinline__ void ldsm4(uint32_t r[4], uint32_t a) {
    asm volatile("ldmatrix.sync.aligned.m8n8.x4.shared.b16 {%0,%1,%2,%3}, [%4];"
        : "=r"(r[0]), "=r"(r[1]), "=r"(r[2]), "=r"(r[3]) : "r"(a));
}
__device__ __forceinline__ void ldsm4t(uint32_t r[4], uint32_t a) {
    asm volatile("ldmatrix.sync.aligned.m8n8.x4.trans.shared.b16 {%0,%1,%2,%3}, [%4];"
        : "=r"(r[0]), "=r"(r[1]), "=r"(r[2]), "=r"(r[3]) : "r"(a));
}
__device__ __forceinline__ void mma16816(float* c, const uint32_t* a, const uint32_t* b) {
    asm volatile("mma.sync.aligned.m16n8k16.row.col.f32.f16.f16.f32 "
        "{%0,%1,%2,%3}, {%4,%5,%6,%7}, {%8,%9}, {%0,%1,%2,%3};"
        : "+f"(c[0]), "+f"(c[1]), "+f"(c[2]), "+f"(c[3])
        : "r"(a[0]), "r"(a[1]), "r"(a[2]), "r"(a[3]), "r"(b[0]), "r"(b[1]));
}
__device__ __forceinline__ uint32_t h2ex2(uint32_t x) {
    uint32_t r;
    asm("ex2.approx.f16x2 %0, %1;" : "=r"(r) : "r"(x));
    return r;
}
__device__ __forceinline__ uint32_t packh2(float a, float b) {
    __half2 h = __floats2half2_rn(a, b);
    return *reinterpret_cast<uint32_t*>(&h);
}

#define CPA16(dst, src) \
    asm volatile("cp.async.cg.shared.global [%0], [%1], 16;" \
        :: "r"((uint32_t)(dst)), "l"((const void*)(src)) : "memory")
#define CPC()  asm volatile("cp.async.commit_group;" ::: "memory")
#define CPW0() asm volatile("cp.async.wait_group 0;" ::: "memory")
#define CPW1() asm volatile("cp.async.wait_group 1;" ::: "memory")

// ---------------------------------------------------------------------------
// Fused front kernel: grid (1024, 5), 256 threads.  (frozen from R13)
//   y = 0..2 : QKV projection (pure fp16 MMA), which = y
//   y = 3    : mask bit-packing (8 chunks per block)
//   y = 4    : Wo fp32 -> fp16 conversion
// ---------------------------------------------------------------------------
#define FRONT_SMEM 24576

__global__ __launch_bounds__(256) void front_kernel(
    const float* __restrict__ vin, const float* __restrict__ kin,
    const float* __restrict__ qin,
    const float* __restrict__ Wv, const float* __restrict__ Wk,
    const float* __restrict__ Wq,
    const int* __restrict__ mask, const float* __restrict__ wo)
{
    const int role = blockIdx.y;
    const int tid = threadIdx.x;

    if (role == 3) {
        #pragma unroll
        for (int it = 0; it < 8; it++) {
            size_t base = (((size_t)blockIdx.x * 8 + it) * 256 + tid) * 4;
            int4 v = *reinterpret_cast<const int4*>(mask + base);
            uint32_t nib = (uint32_t)(v.x != 0) | ((uint32_t)(v.y != 0) << 1)
                         | ((uint32_t)(v.z != 0) << 2) | ((uint32_t)(v.w != 0) << 3);
            nib |= __shfl_xor_sync(0xffffffffu, nib, 1) << 4;
            nib |= __shfl_xor_sync(0xffffffffu, nib, 2) << 8;
            nib |= __shfl_xor_sync(0xffffffffu, nib, 4) << 16;
            if ((tid & 7) == 0) g_mb[base >> 5] = nib;
        }
        return;
    }
    if (role == 4) {
        size_t i = ((size_t)blockIdx.x * 256 + tid) * 4;
        float4 f = *reinterpret_cast<const float4*>(wo + i);
        uint32_t u0 = packh2(f.x, f.y), u1 = packh2(f.z, f.w);
        *reinterpret_cast<uint2*>(g_wo + i) = make_uint2(u0, u1);
        return;
    }

    extern __shared__ char smc[];
    const uint32_t sb = smem_u32(smc);
    const uint32_t AS = sb, WS = sb + 16384;

    const int which = role;
    const float* in = (which == 0) ? vin : (which == 1) ? kin : qin;
    const float* W  = (which == 0) ? Wv  : (which == 1) ? Wk  : Wq;
    __half* outp    = (which == 0) ? g_v : (which == 1) ? g_k : g_q;
    const float wscale = (which == 2) ? XSCALE : 1.0f;

    const int m0 = blockIdx.x * 128;
    const int w = tid >> 5, L = tid & 31;

    for (int c = tid; c < 1024; c += 256) {
        int r = c >> 3, c0 = (c & 7) * 8;
        const float4* s = reinterpret_cast<const float4*>(in + (size_t)(m0 + r) * 64 + c0);
        float4 f0 = s[0], f1 = s[1];
        uint32_t u0 = packh2(f0.x, f0.y), u1 = packh2(f0.z, f0.w);
        uint32_t u2 = packh2(f1.x, f1.y), u3 = packh2(f1.z, f1.w);
        *reinterpret_cast<uint4*>(smc + SWZ(r * 128 + c0 * 2)) = make_uint4(u0, u1, u2, u3);
    }
    for (int c = tid; c < 512; c += 256) {
        int r = c >> 3, c0 = (c & 7) * 8;
        const float4* s = reinterpret_cast<const float4*>(W + (size_t)r * 64 + c0);
        float4 f0 = s[0], f1 = s[1];
        uint32_t u0 = packh2(f0.x * wscale, f0.y * wscale);
        uint32_t u1 = packh2(f0.z * wscale, f0.w * wscale);
        uint32_t u2 = packh2(f1.x * wscale, f1.y * wscale);
        uint32_t u3 = packh2(f1.z * wscale, f1.w * wscale);
        *reinterpret_cast<uint4*>(smc + 16384 + SWZ(r * 128 + c0 * 2)) = make_uint4(u0, u1, u2, u3);
    }
    __syncthreads();

    float acc[8][4] = {};
    const int lr = (L & 7) + ((L >> 3) & 1) * 8;
    const int lc = ((L >> 4) & 1) * 16;
    const int br = ((L >> 4) & 1) * 8 + (L & 7);
    const int bc = ((L >> 3) & 1) * 16;

    #pragma unroll
    for (int ks = 0; ks < 4; ks++) {
        uint32_t a[4];
        ldsm4(a, AS + SWZ((w * 16 + lr) * 128 + ks * 32 + lc));
        #pragma unroll
        for (int p = 0; p < 4; p++) {
            uint32_t b[4];
            ldsm4(b, WS + SWZ((p * 16 + br) * 128 + ks * 32 + bc));
            mma16816(acc[2*p],   a, &b[0]);
            mma16816(acc[2*p+1], a, &b[2]);
        }
    }

    const int t4 = L >> 2, t2 = (L & 3) * 2;
    __syncthreads();
    {
        const int row0 = w * 16 + t4, row1 = row0 + 8;
        #pragma unroll
        for (int f = 0; f < 8; f++) {
            int colb = (f * 8 + t2) * 2;
            uint32_t u0 = packh2(acc[f][0], acc[f][1]);
            uint32_t u1 = packh2(acc[f][2], acc[f][3]);
            *reinterpret_cast<uint32_t*>(smc + SWZ(row0 * 128 + colb)) = u0;
            *reinterpret_cast<uint32_t*>(smc + SWZ(row1 * 128 + colb)) = u1;
        }
    }
    __syncthreads();
    {
        const int rr = tid >> 1, hh = tid & 1;
        const int m = m0 + rr;
        const int hi = m & 15, li = (m >> 4) & 1023, ni = m >> 14;
        size_t base = ((size_t)((ni * 16 + hi) * 1024 + li)) * 64 + hh * 32;
        #pragma unroll
        for (int j = 0; j < 4; j++) {
            uint4 v = *reinterpret_cast<uint4*>(smc + SWZ(rr * 128 + hh * 64 + j * 16));
            *reinterpret_cast<uint4*>(outp + base + j * 8) = v;
        }
    }
}

// ---------------------------------------------------------------------------
// Flash attention: block = (128 q rows, head, batch); 8 warps x 16 rows.
// K-tiles of 128 (processed as two 64-col chunks with the known-good R9 inner
// body). 3-buffer cp.async ring of 32K bufs, ONE barrier per 128-tile
// (8 barriers total). Prefetch (nt+2) post-barrier into buf (nt-1)%3.
// smem: Q 16K | ring 3 x {K 16K, V 16K} = 112K; 2 CTAs/SM (224K <= 227K).
// ---------------------------------------------------------------------------
#define ATTN_SMEM 114688

__global__ __launch_bounds__(256, 2) void attn_mma()
{
    extern __shared__ char smc[];
    const uint32_t sb = smem_u32(smc);
    const uint32_t QS = sb;
    const uint32_t RING = sb + 16384;

    const int q0 = blockIdx.x * 128;
    const int h  = blockIdx.y;
    const int n  = blockIdx.z;
    const int tid = threadIdx.x;
    const int w = tid >> 5, L = tid & 31;

    const size_t head = (size_t)(n * NH + h) * SEQL * 64;
    const __half* qp = g_q + head;
    const __half* kp = g_k + head;
    const __half* vp = g_v + head;

    // prologue: group1 = Q + tile0 (k rows 0..127); group2 = tile1 (128..255)
    for (int c = tid; c < 1024; c += 256) {
        int r = c >> 3, cb = (c & 7) * 16;
        CPA16(QS + SWZ(r * 128 + cb), (const char*)(qp + (size_t)(q0 + r) * 64) + cb);
    }
    for (int c = tid; c < 1024; c += 256) {
        int r = c >> 3, cb = (c & 7) * 16;
        uint32_t off = SWZ(r * 128 + cb);
        size_t go = (size_t)r * 64;
        CPA16(RING + off,         (const char*)(kp + go) + cb);
        CPA16(RING + 16384 + off, (const char*)(vp + go) + cb);
    }
    CPC();
    for (int c = tid; c < 1024; c += 256) {
        int r = c >> 3, cb = (c & 7) * 16;
        uint32_t off = SWZ(r * 128 + cb);
        size_t go = (size_t)(128 + r) * 64;
        CPA16(RING + 32768 + off,         (const char*)(kp + go) + cb);
        CPA16(RING + 32768 + 16384 + off, (const char*)(vp + go) + cb);
    }
    CPC();

    float o[8][4] = {};
    float lacc[4] = {};
    uint32_t aq[4][4];
    const uint32_t ones_b[2] = { 0x3C003C00u, 0x3C003C00u };

    const int lr = (L & 7) + ((L >> 3) & 1) * 8;
    const int lc = ((L >> 4) & 1) * 16;
    const int brr = ((L >> 4) & 1) * 8 + (L & 7);
    const int bcc = ((L >> 3) & 1) * 16;
    const int t4 = L >> 2, t2 = (L & 3) * 2;
    const int qa = q0 + w * 16 + t4, qb = qa + 8;

    const unsigned* mrow_a = g_mb + ((size_t)(n * SEQL + qa)) * 32;
    const unsigned* mrow_b = g_mb + ((size_t)(n * SEQL + qb)) * 32;

    int cur = 0, pre = 2;   // nt%3, (nt+2)%3
    for (int nt = 0; nt < 8; nt++) {
        // tile nt complete (pending: nt, nt+1)
        if (nt < 7) { CPW1(); } else { CPW0(); }
        __syncthreads();   // single barrier per 128-tile

        // prefetch tile nt+2 into buf (nt+2)%3 == (nt-1)%3 (safe post-barrier)
        if (nt < 6) {
            uint32_t B = RING + pre * 32768;
            const int k0 = (nt + 2) * 128;
            for (int c = tid; c < 1024; c += 256) {
                int r = c >> 3, cb = (c & 7) * 16;
                uint32_t off = SWZ(r * 128 + cb);
                size_t go = (size_t)(k0 + r) * 64;
                CPA16(B + off,         (const char*)(kp + go) + cb);
                CPA16(B + 16384 + off, (const char*)(vp + go) + cb);
            }
            CPC();
        }

        // prefetch 4 mask words per row (covers both 64-col chunks)
        unsigned wa[4], wb[4];
        #pragma unroll
        for (int j = 0; j < 4; j++) { wa[j] = mrow_a[nt * 4 + j]; wb[j] = mrow_b[nt * 4 + j]; }

        if (nt == 0) {
            #pragma unroll
            for (int ks = 0; ks < 4; ks++)
                ldsm4(aq[ks], QS + SWZ((w * 16 + lr) * 128 + ks * 32 + lc));
        }

        const uint32_t KB0 = RING + cur * 32768;
        const uint32_t VB0 = KB0 + 16384;

        #pragma unroll
        for (int c2 = 0; c2 < 2; c2++) {
            const uint32_t KB = KB0 + c2 * 8192;   // 64 k-rows per chunk
            const uint32_t VB = VB0 + c2 * 8192;

            // S = Q K^T  (already log2-scaled)
            float s[8][4] = {};
            #pragma unroll
            for (int ks = 0; ks < 4; ks++) {
                #pragma unroll
                for (int p = 0; p < 4; p++) {
                    uint32_t bh[4];
                    ldsm4(bh, KB + SWZ((p * 16 + brr) * 128 + ks * 32 + bcc));
                    mma16816(s[2*p],   aq[ks], &bh[0]);
                    mma16816(s[2*p+1], aq[ks], &bh[2]);
                }
            }

            // mask-select -> pack -> ex2 (straight-line)
            uint32_t preg[8][2];
            #pragma unroll
            for (int f = 0; f < 8; f++) {
                unsigned wA = (f < 4) ? wa[c2 * 2] : wa[c2 * 2 + 1];
                unsigned wB = (f < 4) ? wb[c2 * 2] : wb[c2 * 2 + 1];
                int bit = (f & 3) * 8 + t2;
                float xa0 = ((wA >> bit) & 1)       ? s[f][0] : -100.f;
                float xa1 = ((wA >> (bit + 1)) & 1) ? s[f][1] : -100.f;
                float xb0 = ((wB >> bit) & 1)       ? s[f][2] : -100.f;
                float xb1 = ((wB >> (bit + 1)) & 1) ? s[f][3] : -100.f;
                preg[f][0] = h2ex2(packh2(xa0, xa1));
                preg[f][1] = h2ex2(packh2(xb0, xb1));
            }

            // O += P V ; l += P @ ones
            #pragma unroll
            for (int ks = 0; ks < 4; ks++) {
                uint32_t ph[4] = { preg[2*ks][0], preg[2*ks][1],
                                   preg[2*ks+1][0], preg[2*ks+1][1] };
                mma16816(lacc, ph, ones_b);
                #pragma unroll
                for (int p = 0; p < 4; p++) {
                    uint32_t bh[4];
                    ldsm4t(bh, VB + SWZ((ks * 16 + lr) * 128 + p * 32 + lc));
                    mma16816(o[2*p],   ph, &bh[0]);
                    mma16816(o[2*p+1], ph, &bh[2]);
                }
            }
        }

        cur = (cur == 2) ? 0 : cur + 1;
        pre = (pre == 2) ? 0 : pre + 1;
    }

    // epilogue: l complete per row; normalize, store
    float ia = 1.0f / lacc[0], ib = 1.0f / lacc[2];
    size_t ba = ((size_t)(n * SEQL + qa)) * EMB + h * 64;
    size_t bb = ((size_t)(n * SEQL + qb)) * EMB + h * 64;
    #pragma unroll
    for (int f = 0; f < 8; f++) {
        int col = f * 8 + t2;
        *reinterpret_cast<uint32_t*>(g_ao + ba + col) = packh2(o[f][0] * ia, o[f][1] * ia);
        *reinterpret_cast<uint32_t*>(g_ao + bb + col) = packh2(o[f][2] * ib, o[f][3] * ib);
    }
}

// ---------------------------------------------------------------------------
// Output projection (frozen from R13): (8192 x 1024) @ (1024 x 1024)^T + bias,
// pure fp16 1-term. Tile 128x128, 256 threads, K chunks of 64, 3-buffer ring,
// ONE barrier per tile. smem: 3 x 32K = 96K; 2 CTAs/SM.
// ---------------------------------------------------------------------------
#define OUT_SMEM 98304

__global__ __launch_bounds__(256, 2) void outproj_mma(
    const float* __restrict__ bo, float* __restrict__ out)
{
    extern __shared__ char smc[];
    const uint32_t sb = smem_u32(smc);

    const int m0 = blockIdx.x * 128;
    const int e0 = blockIdx.y * 128;
    const int tid = threadIdx.x;
    const int w = tid >> 5, L = tid & 31;

    #pragma unroll
    for (int pk = 0; pk < 2; pk++) {
        uint32_t B = sb + pk * 32768;
        const int k0 = pk * 64;
        for (int c = tid; c < 1024; c += 256) {
            int r = c >> 3, cb = (c & 7) * 16;
            uint32_t off = SWZ(r * 128 + cb);
            CPA16(B + off,         (const char*)(g_ao + (size_t)(m0 + r) * EMB + k0) + cb);
            CPA16(B + 16384 + off, (const char*)(g_wo + (size_t)(e0 + r) * EMB + k0) + cb);
        }
        CPC();
    }

    float acc[16][4] = {};
    const int lr = (L & 7) + ((L >> 3) & 1) * 8;
    const int lc = ((L >> 4) & 1) * 16;
    const int brr = ((L >> 4) & 1) * 8 + (L & 7);
    const int bcc = ((L >> 3) & 1) * 16;

    int cur = 0, pre = 2;
    for (int kt = 0; kt < 16; kt++) {
        if (kt < 15) { CPW1(); } else { CPW0(); }
        __syncthreads();

        if (kt < 14) {
            uint32_t B = sb + pre * 32768;
            const int k0 = (kt + 2) * 64;
            for (int c = tid; c < 1024; c += 256) {
                int r = c >> 3, cb = (c & 7) * 16;
                uint32_t off = SWZ(r * 128 + cb);
                CPA16(B + off,         (const char*)(g_ao + (size_t)(m0 + r) * EMB + k0) + cb);
                CPA16(B + 16384 + off, (const char*)(g_wo + (size_t)(e0 + r) * EMB + k0) + cb);
            }
            CPC();
        }

        const uint32_t AS = sb + cur * 32768;
        const uint32_t BS = AS + 16384;

        #pragma unroll
        for (int ks = 0; ks < 4; ks++) {
            uint32_t a[4];
            ldsm4(a, AS + SWZ((w * 16 + lr) * 128 + ks * 32 + lc));
            #pragma unroll
            for (int p = 0; p < 8; p++) {
                uint32_t b[4];
                ldsm4(b, BS + SWZ((p * 16 + brr) * 128 + ks * 32 + bcc));
                mma16816(acc[2*p],   a, &b[0]);
                mma16816(acc[2*p+1], a, &b[2]);
            }
        }

        cur = (cur == 2) ? 0 : cur + 1;
        pre = (pre == 2) ? 0 : pre + 1;
    }

    const int t4 = L >> 2, t2 = (L & 3) * 2;
    const int r0 = m0 + w * 16 + t4, r1 = r0 + 8;
    #pragma unroll
    for (int f = 0; f < 16; f++) {
        int col = e0 + f * 8 + t2;
        float b0v = bo[col], b1v = bo[col + 1];
        float2 v0 = make_float2(acc[f][0] + b0v, acc[f][1] + b1v);
        float2 v1 = make_float2(acc[f][2] + b0v, acc[f][3] + b1v);
        *reinterpret_cast<float2*>(out + (size_t)r0 * EMB + col) = v0;
        *reinterpret_cast<float2*>(out + (size_t)r1 * EMB + col) = v1;
    }
}

// ---------------------------------------------------------------------------
extern "C" void kernel_launch(void* const* d_in, const int* in_sizes, int n_in,
                              void* d_out, int out_size)
{
    const float* values = (const float*)d_in[0];
    const float* keys   = (const float*)d_in[1];
    const float* query  = (const float*)d_in[2];
    const int*   mask   = (const int*)d_in[3];
    const float* Wv     = (const float*)d_in[4];
    const float* Wk     = (const float*)d_in[5];
    const float* Wq     = (const float*)d_in[6];
    const float* Wo     = (const float*)d_in[7];
    const float* bo     = (const float*)d_in[8];
    float* out = (float*)d_out;
    (void)in_sizes; (void)n_in; (void)out_size;

    cudaFuncSetAttribute(front_kernel, cudaFuncAttributeMaxDynamicSharedMemorySize, FRONT_SMEM);
    cudaFuncSetAttribute(attn_mma,     cudaFuncAttributeMaxDynamicSharedMemorySize, ATTN_SMEM);
    cudaFuncSetAttribute(outproj_mma,  cudaFuncAttributeMaxDynamicSharedMemorySize, OUT_SMEM);

    front_kernel<<<dim3(1024, 5), 256, FRONT_SMEM>>>(values, keys, query,
                                                     Wv, Wk, Wq, mask, Wo);
    attn_mma<<<dim3(SEQL/128, NH, NB), 256, ATTN_SMEM>>>();
    outproj_mma<<<dim3(64, 8), 256, OUT_SMEM>>>(bo, out);
}

// round 15
// speedup vs baseline: 1.0387x; 1.0387x over previous
#include <cuda_runtime.h>
#include <cuda_fp16.h>
#include <cstdint>
#include <float.h>

#define NB   8
#define SEQL 1024
#define NH   16
#define HD   64
#define EMB  1024

// ---------------------------------------------------------------------------
// Device scratch (allocation-free rule)
// ---------------------------------------------------------------------------
__device__ __half g_q [NB*NH*SEQL*HD];     // projected Q (fp16, pre-scaled by XSCALE)
__device__ __half g_k [NB*NH*SEQL*HD];     // projected K (fp16)
__device__ __half g_v [NB*NH*SEQL*HD];     // projected V (fp16)
__device__ __half g_ao[NB*SEQL*EMB];       // attention out (fp16) [n][l][e]
__device__ __half g_wo[EMB*EMB];           // Wo fp16
__device__ unsigned g_mb[NB*SEQL*SEQL/32]; // packed mask bits

// log2 domain: softmax(z/32) = exp2(z * C) / sum, C = log2(e)/32, folded into Wq.
#define XSCALE 0.0450842139f          /* 0.03125 * log2(e) */

// ---------------------------------------------------------------------------
// helpers
// ---------------------------------------------------------------------------
__device__ __forceinline__ uint32_t smem_u32(const void* p) {
    uint32_t a;
    asm("{ .reg .u64 t; cvta.to.shared.u64 t, %1; cvt.u32.u64 %0, t; }"
        : "=r"(a) : "l"(p));
    return a;
}

#define SWZ(o) ((o) ^ ((((uint32_t)(o)) >> 3) & 0x70u))

__device__ __forceinline__ void ldsm4(uint32_t r[4], uint32_t a) {
    asm volatile("ldmatrix.sync.aligned.m8n8.x4.shared.b16 {%0,%1,%2,%3}, [%4];"
        : "=r"(r[0]), "=r"(r[1]), "=r"(r[2]), "=r"(r[3]) : "r"(a));
}
__device__ __forceinline__ void ldsm4t(uint32_t r[4], uint32_t a) {
    asm volatile("ldmatrix.sync.aligned.m8n8.x4.trans.shared.b16 {%0,%1,%2,%3}, [%4];"
        : "=r"(r[0]), "=r"(r[1]), "=r"(r[2]), "=r"(r[3]) : "r"(a));
}
__device__ __forceinline__ void mma16816(float* c, const uint32_t* a, const uint32_t* b) {
    asm volatile("mma.sync.aligned.m16n8k16.row.col.f32.f16.f16.f32 "
        "{%0,%1,%2,%3}, {%4,%5,%6,%7}, {%8,%9}, {%0,%1,%2,%3};"
        : "+f"(c[0]), "+f"(c[1]), "+f"(c[2]), "+f"(c[3])
        : "r"(a[0]), "r"(a[1]), "r"(a[2]), "r"(a[3]), "r"(b[0]), "r"(b[1]));
}
__device__ __forceinline__ uint32_t h2ex2(uint32_t x) {
    uint32_t r;
    asm("ex2.approx.f16x2 %0, %1;" : "=r"(r) : "r"(x));
    return r;
}
__device__ __forceinline__ uint32_t packh2(float a, float b) {
    __half2 h = __floats2half2_rn(a, b);
    return *reinterpret_cast<uint32_t*>(&h);
}

#define CPA16(dst, src) \
    asm volatile("cp.async.cg.shared.global [%0], [%1], 16;" \
        :: "r"((uint32_t)(dst)), "l"((const void*)(src)) : "memory")
#define CPC()  asm volatile("cp.async.commit_group;" ::: "memory")
#define CPW0() asm volatile("cp.async.wait_group 0;" ::: "memory")
#define CPW1() asm volatile("cp.async.wait_group 1;" ::: "memory")

// ---------------------------------------------------------------------------
// Fused front kernel: grid (1024, 5), 256 threads.  (frozen from R13)
//   y = 0..2 : QKV projection (pure fp16 MMA), which = y
//   y = 3    : mask bit-packing (8 chunks per block)
//   y = 4    : Wo fp32 -> fp16 conversion
// ---------------------------------------------------------------------------
#define FRONT_SMEM 24576

__global__ __launch_bounds__(256) void front_kernel(
    const float* __restrict__ vin, const float* __restrict__ kin,
    const float* __restrict__ qin,
    const float* __restrict__ Wv, const float* __restrict__ Wk,
    const float* __restrict__ Wq,
    const int* __restrict__ mask, const float* __restrict__ wo)
{
    const int role = blockIdx.y;
    const int tid = threadIdx.x;

    if (role == 3) {
        #pragma unroll
        for (int it = 0; it < 8; it++) {
            size_t base = (((size_t)blockIdx.x * 8 + it) * 256 + tid) * 4;
            int4 v = *reinterpret_cast<const int4*>(mask + base);
            uint32_t nib = (uint32_t)(v.x != 0) | ((uint32_t)(v.y != 0) << 1)
                         | ((uint32_t)(v.z != 0) << 2) | ((uint32_t)(v.w != 0) << 3);
            nib |= __shfl_xor_sync(0xffffffffu, nib, 1) << 4;
            nib |= __shfl_xor_sync(0xffffffffu, nib, 2) << 8;
            nib |= __shfl_xor_sync(0xffffffffu, nib, 4) << 16;
            if ((tid & 7) == 0) g_mb[base >> 5] = nib;
        }
        return;
    }
    if (role == 4) {
        size_t i = ((size_t)blockIdx.x * 256 + tid) * 4;
        float4 f = *reinterpret_cast<const float4*>(wo + i);
        uint32_t u0 = packh2(f.x, f.y), u1 = packh2(f.z, f.w);
        *reinterpret_cast<uint2*>(g_wo + i) = make_uint2(u0, u1);
        return;
    }

    extern __shared__ char smc[];
    const uint32_t sb = smem_u32(smc);
    const uint32_t AS = sb, WS = sb + 16384;

    const int which = role;
    const float* in = (which == 0) ? vin : (which == 1) ? kin : qin;
    const float* W  = (which == 0) ? Wv  : (which == 1) ? Wk  : Wq;
    __half* outp    = (which == 0) ? g_v : (which == 1) ? g_k : g_q;
    const float wscale = (which == 2) ? XSCALE : 1.0f;

    const int m0 = blockIdx.x * 128;
    const int w = tid >> 5, L = tid & 31;

    for (int c = tid; c < 1024; c += 256) {
        int r = c >> 3, c0 = (c & 7) * 8;
        const float4* s = reinterpret_cast<const float4*>(in + (size_t)(m0 + r) * 64 + c0);
        float4 f0 = s[0], f1 = s[1];
        uint32_t u0 = packh2(f0.x, f0.y), u1 = packh2(f0.z, f0.w);
        uint32_t u2 = packh2(f1.x, f1.y), u3 = packh2(f1.z, f1.w);
        *reinterpret_cast<uint4*>(smc + SWZ(r * 128 + c0 * 2)) = make_uint4(u0, u1, u2, u3);
    }
    for (int c = tid; c < 512; c += 256) {
        int r = c >> 3, c0 = (c & 7) * 8;
        const float4* s = reinterpret_cast<const float4*>(W + (size_t)r * 64 + c0);
        float4 f0 = s[0], f1 = s[1];
        uint32_t u0 = packh2(f0.x * wscale, f0.y * wscale);
        uint32_t u1 = packh2(f0.z * wscale, f0.w * wscale);
        uint32_t u2 = packh2(f1.x * wscale, f1.y * wscale);
        uint32_t u3 = packh2(f1.z * wscale, f1.w * wscale);
        *reinterpret_cast<uint4*>(smc + 16384 + SWZ(r * 128 + c0 * 2)) = make_uint4(u0, u1, u2, u3);
    }
    __syncthreads();

    float acc[8][4] = {};
    const int lr = (L & 7) + ((L >> 3) & 1) * 8;
    const int lc = ((L >> 4) & 1) * 16;
    const int br = ((L >> 4) & 1) * 8 + (L & 7);
    const int bc = ((L >> 3) & 1) * 16;

    #pragma unroll
    for (int ks = 0; ks < 4; ks++) {
        uint32_t a[4];
        ldsm4(a, AS + SWZ((w * 16 + lr) * 128 + ks * 32 + lc));
        #pragma unroll
        for (int p = 0; p < 4; p++) {
            uint32_t b[4];
            ldsm4(b, WS + SWZ((p * 16 + br) * 128 + ks * 32 + bc));
            mma16816(acc[2*p],   a, &b[0]);
            mma16816(acc[2*p+1], a, &b[2]);
        }
    }

    const int t4 = L >> 2, t2 = (L & 3) * 2;
    __syncthreads();
    {
        const int row0 = w * 16 + t4, row1 = row0 + 8;
        #pragma unroll
        for (int f = 0; f < 8; f++) {
            int colb = (f * 8 + t2) * 2;
            uint32_t u0 = packh2(acc[f][0], acc[f][1]);
            uint32_t u1 = packh2(acc[f][2], acc[f][3]);
            *reinterpret_cast<uint32_t*>(smc + SWZ(row0 * 128 + colb)) = u0;
            *reinterpret_cast<uint32_t*>(smc + SWZ(row1 * 128 + colb)) = u1;
        }
    }
    __syncthreads();
    {
        const int rr = tid >> 1, hh = tid & 1;
        const int m = m0 + rr;
        const int hi = m & 15, li = (m >> 4) & 1023, ni = m >> 14;
        size_t base = ((size_t)((ni * 16 + hi) * 1024 + li)) * 64 + hh * 32;
        #pragma unroll
        for (int j = 0; j < 4; j++) {
            uint4 v = *reinterpret_cast<uint4*>(smc + SWZ(rr * 128 + hh * 64 + j * 16));
            *reinterpret_cast<uint4*>(outp + base + j * 8) = v;
        }
    }
}

// ---------------------------------------------------------------------------
// Flash attention: block = (128 q rows, head, batch); 8 warps x 16 rows.
// K-tiles of 64. 3-buffer cp.async ring (R13 known-good), ONE barrier/tile.
// R15 tweaks: mask LDGs hoisted above the cp.async wait; epilogue staged
// through QS (free after nt==0) for coalesced STG.128 output.
// smem: Q 16K | ring 3 x {K 8K, V 8K} = 64K; 2 CTAs/SM.
// ---------------------------------------------------------------------------
#define ATTN_SMEM 65536

__global__ __launch_bounds__(256, 2) void attn_mma()
{
    extern __shared__ char smc[];
    const uint32_t sb = smem_u32(smc);
    const uint32_t QS = sb;
    const uint32_t RING = sb + 16384;

    const int q0 = blockIdx.x * 128;
    const int h  = blockIdx.y;
    const int n  = blockIdx.z;
    const int tid = threadIdx.x;
    const int w = tid >> 5, L = tid & 31;

    const size_t head = (size_t)(n * NH + h) * SEQL * 64;
    const __half* qp = g_q + head;
    const __half* kp = g_k + head;
    const __half* vp = g_v + head;

    // prologue: group0 = Q + tile0 -> buf0; group1 = tile1 -> buf1
    for (int c = tid; c < 1024; c += 256) {
        int r = c >> 3, cb = (c & 7) * 16;
        CPA16(QS + SWZ(r * 128 + cb), (const char*)(qp + (size_t)(q0 + r) * 64) + cb);
    }
    for (int c = tid; c < 512; c += 256) {
        int r = c >> 3, cb = (c & 7) * 16;
        uint32_t off = SWZ(r * 128 + cb);
        size_t go = (size_t)r * 64;
        CPA16(RING + off,        (const char*)(kp + go) + cb);
        CPA16(RING + 8192 + off, (const char*)(vp + go) + cb);
    }
    CPC();
    for (int c = tid; c < 512; c += 256) {
        int r = c >> 3, cb = (c & 7) * 16;
        uint32_t off = SWZ(r * 128 + cb);
        size_t go = (size_t)(64 + r) * 64;
        CPA16(RING + 16384 + off,        (const char*)(kp + go) + cb);
        CPA16(RING + 16384 + 8192 + off, (const char*)(vp + go) + cb);
    }
    CPC();

    float o[8][4] = {};
    float lacc[4] = {};
    uint32_t aq[4][4];
    const uint32_t ones_b[2] = { 0x3C003C00u, 0x3C003C00u };

    const int lr = (L & 7) + ((L >> 3) & 1) * 8;
    const int lc = ((L >> 4) & 1) * 16;
    const int brr = ((L >> 4) & 1) * 8 + (L & 7);
    const int bcc = ((L >> 3) & 1) * 16;
    const int t4 = L >> 2, t2 = (L & 3) * 2;
    const int qa = q0 + w * 16 + t4, qb = qa + 8;

    const unsigned* mrow_a = g_mb + ((size_t)(n * SEQL + qa)) * 32;
    const unsigned* mrow_b = g_mb + ((size_t)(n * SEQL + qb)) * 32;

    int cur = 0, pre = 2;   // kt%3, (kt+2)%3
    for (int kt = 0; kt < 16; kt++) {
        // mask LDGs first: latency overlaps the cp.async drain + barrier
        unsigned wa0 = mrow_a[kt * 2], wa1 = mrow_a[kt * 2 + 1];
        unsigned wb0 = mrow_b[kt * 2], wb1 = mrow_b[kt * 2 + 1];

        // group kt must be complete (pending: kt, kt+1)
        if (kt < 15) { CPW1(); } else { CPW0(); }
        __syncthreads();   // single barrier: kt data visible AND kt-1 reads done

        // prefetch kt+2 into buf (kt+2)%3 == (kt-1)%3 (safe after barrier)
        if (kt < 14) {
            uint32_t B = RING + pre * 16384;
            const int k0 = (kt + 2) * 64;
            for (int c = tid; c < 512; c += 256) {
                int r = c >> 3, cb = (c & 7) * 16;
                uint32_t off = SWZ(r * 128 + cb);
                size_t go = (size_t)(k0 + r) * 64;
                CPA16(B + off,        (const char*)(kp + go) + cb);
                CPA16(B + 8192 + off, (const char*)(vp + go) + cb);
            }
            CPC();
        }

        if (kt == 0) {
            #pragma unroll
            for (int ks = 0; ks < 4; ks++)
                ldsm4(aq[ks], QS + SWZ((w * 16 + lr) * 128 + ks * 32 + lc));
        }

        const uint32_t KB = RING + cur * 16384;
        const uint32_t VB = KB + 8192;

        // S = Q K^T  (already log2-scaled)
        float s[8][4] = {};
        #pragma unroll
        for (int ks = 0; ks < 4; ks++) {
            #pragma unroll
            for (int p = 0; p < 4; p++) {
                uint32_t bh[4];
                ldsm4(bh, KB + SWZ((p * 16 + brr) * 128 + ks * 32 + bcc));
                mma16816(s[2*p],   aq[ks], &bh[0]);
                mma16816(s[2*p+1], aq[ks], &bh[2]);
            }
        }

        // mask-select -> pack -> ex2 (straight-line)
        uint32_t preg[8][2];
        #pragma unroll
        for (int f = 0; f < 8; f++) {
            unsigned wA = (f < 4) ? wa0 : wa1;
            unsigned wB = (f < 4) ? wb0 : wb1;
            int bit = (f & 3) * 8 + t2;
            float xa0 = ((wA >> bit) & 1)       ? s[f][0] : -100.f;
            float xa1 = ((wA >> (bit + 1)) & 1) ? s[f][1] : -100.f;
            float xb0 = ((wB >> bit) & 1)       ? s[f][2] : -100.f;
            float xb1 = ((wB >> (bit + 1)) & 1) ? s[f][3] : -100.f;
            preg[f][0] = h2ex2(packh2(xa0, xa1));
            preg[f][1] = h2ex2(packh2(xb0, xb1));
        }

        // O += P V ; l += P @ ones
        #pragma unroll
        for (int ks = 0; ks < 4; ks++) {
            uint32_t ph[4] = { preg[2*ks][0], preg[2*ks][1],
                               preg[2*ks+1][0], preg[2*ks+1][1] };
            mma16816(lacc, ph, ones_b);
            #pragma unroll
            for (int p = 0; p < 4; p++) {
                uint32_t bh[4];
                ldsm4t(bh, VB + SWZ((ks * 16 + lr) * 128 + p * 32 + lc));
                mma16816(o[2*p],   ph, &bh[0]);
                mma16816(o[2*p+1], ph, &bh[2]);
            }
        }

        cur = (cur == 2) ? 0 : cur + 1;
        pre = (pre == 2) ? 0 : pre + 1;
    }

    // epilogue: normalize, stage into QS (free since nt==0), coalesced store
    float ia = 1.0f / lacc[0], ib = 1.0f / lacc[2];
    __syncthreads();   // all warps done with ring/QS reads
    {
        const int ra = w * 16 + t4, rb = ra + 8;   // block-local rows
        #pragma unroll
        for (int f = 0; f < 8; f++) {
            int colb = (f * 8 + t2) * 2;
            *reinterpret_cast<uint32_t*>(smc + SWZ(ra * 128 + colb)) =
                packh2(o[f][0] * ia, o[f][1] * ia);
            *reinterpret_cast<uint32_t*>(smc + SWZ(rb * 128 + colb)) =
                packh2(o[f][2] * ib, o[f][3] * ib);
        }
    }
    __syncthreads();
    {
        const int rr = tid >> 1, hh = tid & 1;
        size_t base = ((size_t)(n * SEQL + q0 + rr)) * EMB + h * 64 + hh * 32;
        #pragma unroll
        for (int j = 0; j < 4; j++) {
            uint4 v = *reinterpret_cast<uint4*>(smc + SWZ(rr * 128 + hh * 64 + j * 16));
            *reinterpret_cast<uint4*>(g_ao + base + j * 8) = v;
        }
    }
}

// ---------------------------------------------------------------------------
// Output projection (frozen from R13): (8192 x 1024) @ (1024 x 1024)^T + bias,
// pure fp16 1-term. Tile 128x128, 256 threads, K chunks of 64, 3-buffer ring,
// ONE barrier per tile. smem: 3 x 32K = 96K; 2 CTAs/SM.
// ---------------------------------------------------------------------------
#define OUT_SMEM 98304

__global__ __launch_bounds__(256, 2) void outproj_mma(
    const float* __restrict__ bo, float* __restrict__ out)
{
    extern __shared__ char smc[];
    const uint32_t sb = smem_u32(smc);

    const int m0 = blockIdx.x * 128;
    const int e0 = blockIdx.y * 128;
    const int tid = threadIdx.x;
    const int w = tid >> 5, L = tid & 31;

    #pragma unroll
    for (int pk = 0; pk < 2; pk++) {
        uint32_t B = sb + pk * 32768;
        const int k0 = pk * 64;
        for (int c = tid; c < 1024; c += 256) {
            int r = c >> 3, cb = (c & 7) * 16;
            uint32_t off = SWZ(r * 128 + cb);
            CPA16(B + off,         (const char*)(g_ao + (size_t)(m0 + r) * EMB + k0) + cb);
            CPA16(B + 16384 + off, (const char*)(g_wo + (size_t)(e0 + r) * EMB + k0) + cb);
        }
        CPC();
    }

    float acc[16][4] = {};
    const int lr = (L & 7) + ((L >> 3) & 1) * 8;
    const int lc = ((L >> 4) & 1) * 16;
    const int brr = ((L >> 4) & 1) * 8 + (L & 7);
    const int bcc = ((L >> 3) & 1) * 16;

    int cur = 0, pre = 2;
    for (int kt = 0; kt < 16; kt++) {
        if (kt < 15) { CPW1(); } else { CPW0(); }
        __syncthreads();

        if (kt < 14) {
            uint32_t B = sb + pre * 32768;
            const int k0 = (kt + 2) * 64;
            for (int c = tid; c < 1024; c += 256) {
                int r = c >> 3, cb = (c & 7) * 16;
                uint32_t off = SWZ(r * 128 + cb);
                CPA16(B + off,         (const char*)(g_ao + (size_t)(m0 + r) * EMB + k0) + cb);
                CPA16(B + 16384 + off, (const char*)(g_wo + (size_t)(e0 + r) * EMB + k0) + cb);
            }
            CPC();
        }

        const uint32_t AS = sb + cur * 32768;
        const uint32_t BS = AS + 16384;

        #pragma unroll
        for (int ks = 0; ks < 4; ks++) {
            uint32_t a[4];
            ldsm4(a, AS + SWZ((w * 16 + lr) * 128 + ks * 32 + lc));
            #pragma unroll
            for (int p = 0; p < 8; p++) {
                uint32_t b[4];
                ldsm4(b, BS + SWZ((p * 16 + brr) * 128 + ks * 32 + bcc));
                mma16816(acc[2*p],   a, &b[0]);
                mma16816(acc[2*p+1], a, &b[2]);
            }
        }

        cur = (cur == 2) ? 0 : cur + 1;
        pre = (pre == 2) ? 0 : pre + 1;
    }

    const int t4 = L >> 2, t2 = (L & 3) * 2;
    const int r0 = m0 + w * 16 + t4, r1 = r0 + 8;
    #pragma unroll
    for (int f = 0; f < 16; f++) {
        int col = e0 + f * 8 + t2;
        float b0v = bo[col], b1v = bo[col + 1];
        float2 v0 = make_float2(acc[f][0] + b0v, acc[f][1] + b1v);
        float2 v1 = make_float2(acc[f][2] + b0v, acc[f][3] + b1v);
        *reinterpret_cast<float2*>(out + (size_t)r0 * EMB + col) = v0;
        *reinterpret_cast<float2*>(out + (size_t)r1 * EMB + col) = v1;
    }
}

// ---------------------------------------------------------------------------
extern "C" void kernel_launch(void* const* d_in, const int* in_sizes, int n_in,
                              void* d_out, int out_size)
{
    const float* values = (const float*)d_in[0];
    const float* keys   = (const float*)d_in[1];
    const float* query  = (const float*)d_in[2];
    const int*   mask   = (const int*)d_in[3];
    const float* Wv     = (const float*)d_in[4];
    const float* Wk     = (const float*)d_in[5];
    const float* Wq     = (const float*)d_in[6];
    const float* Wo     = (const float*)d_in[7];
    const float* bo     = (const float*)d_in[8];
    float* out = (float*)d_out;
    (void)in_sizes; (void)n_in; (void)out_size;

    cudaFuncSetAttribute(front_kernel, cudaFuncAttributeMaxDynamicSharedMemorySize, FRONT_SMEM);
    cudaFuncSetAttribute(attn_mma,     cudaFuncAttributeMaxDynamicSharedMemorySize, ATTN_SMEM);
    cudaFuncSetAttribute(outproj_mma,  cudaFuncAttributeMaxDynamicSharedMemorySize, OUT_SMEM);

    front_kernel<<<dim3(1024, 5), 256, FRONT_SMEM>>>(values, keys, query,
                                                     Wv, Wk, Wq, mask, Wo);
    attn_mma<<<dim3(SEQL/128, NH, NB), 256, ATTN_SMEM>>>();
    outproj_mma<<<dim3(64, 8), 256, OUT_SMEM>>>(bo, out);
}

// round 16
// speedup vs baseline: 1.4790x; 1.4240x over previous
#include <cuda_runtime.h>
#include <cuda_fp16.h>
#include <cstdint>
#include <float.h>

#define NB   8
#define SEQL 1024
#define NH   16
#define HD   64
#define EMB  1024

// ---------------------------------------------------------------------------
// Device scratch (allocation-free rule)
// ---------------------------------------------------------------------------
__device__ __half g_q [NB*NH*SEQL*HD];     // projected Q (fp16, pre-scaled by XSCALE)
__device__ __half g_k [NB*NH*SEQL*HD];     // projected K (fp16)
__device__ __half g_v [NB*NH*SEQL*HD];     // projected V (fp16)
__device__ __half g_ao[NB*SEQL*EMB];       // attention out (fp16) [n][l][e]
__device__ __half g_wo[EMB*EMB];           // Wo fp16
__device__ unsigned g_mb[NB*SEQL*SEQL/32]; // packed mask bits

// log2 domain: softmax(z/32) = exp2(z * C) / sum, C = log2(e)/32, folded into Wq.
#define XSCALE 0.0450842139f          /* 0.03125 * log2(e) */

// ---------------------------------------------------------------------------
// helpers
// ---------------------------------------------------------------------------
__device__ __forceinline__ uint32_t smem_u32(const void* p) {
    uint32_t a;
    asm("{ .reg .u64 t; cvta.to.shared.u64 t, %1; cvt.u32.u64 %0, t; }"
        : "=r"(a) : "l"(p));
    return a;
}

#define SWZ(o) ((o) ^ ((((uint32_t)(o)) >> 3) & 0x70u))

__device__ __forceinline__ void ldsm4(uint32_t r[4], uint32_t a) {
    asm volatile("ldmatrix.sync.aligned.m8n8.x4.shared.b16 {%0,%1,%2,%3}, [%4];"
        : "=r"(r[0]), "=r"(r[1]), "=r"(r[2]), "=r"(r[3]) : "r"(a));
}
__device__ __forceinline__ void ldsm4t(uint32_t r[4], uint32_t a) {
    asm volatile("ldmatrix.sync.aligned.m8n8.x4.trans.shared.b16 {%0,%1,%2,%3}, [%4];"
        : "=r"(r[0]), "=r"(r[1]), "=r"(r[2]), "=r"(r[3]) : "r"(a));
}
__device__ __forceinline__ void mma16816(float* c, const uint32_t* a, const uint32_t* b) {
    asm volatile("mma.sync.aligned.m16n8k16.row.col.f32.f16.f16.f32 "
        "{%0,%1,%2,%3}, {%4,%5,%6,%7}, {%8,%9}, {%0,%1,%2,%3};"
        : "+f"(c[0]), "+f"(c[1]), "+f"(c[2]), "+f"(c[3])
        : "r"(a[0]), "r"(a[1]), "r"(a[2]), "r"(a[3]), "r"(b[0]), "r"(b[1]));
}
__device__ __forceinline__ uint32_t h2ex2(uint32_t x) {
    uint32_t r;
    asm("ex2.approx.f16x2 %0, %1;" : "=r"(r) : "r"(x));
    return r;
}
__device__ __forceinline__ uint32_t packh2(float a, float b) {
    __half2 h = __floats2half2_rn(a, b);
    return *reinterpret_cast<uint32_t*>(&h);
}

#define CPA16(dst, src) \
    asm volatile("cp.async.cg.shared.global [%0], [%1], 16;" \
        :: "r"((uint32_t)(dst)), "l"((const void*)(src)) : "memory")
#define CPC()  asm volatile("cp.async.commit_group;" ::: "memory")
#define CPW0() asm volatile("cp.async.wait_group 0;" ::: "memory")
#define CPW1() asm volatile("cp.async.wait_group 1;" ::: "memory")

// ---------------------------------------------------------------------------
// Fused front kernel: grid (1024, 5), 256 threads.
//   y = 0..2 : QKV projection (pure fp16 MMA), which = y
//   y = 3    : mask bit-packing (8 chunks per block)
//   y = 4    : Wo fp32 -> fp16 conversion
// Proj epilogue stages results through smem for coalesced STG.128 output.
// smem (proj role): A 16K | W 8K = 24K
// ---------------------------------------------------------------------------
#define FRONT_SMEM 24576

__global__ __launch_bounds__(256) void front_kernel(
    const float* __restrict__ vin, const float* __restrict__ kin,
    const float* __restrict__ qin,
    const float* __restrict__ Wv, const float* __restrict__ Wk,
    const float* __restrict__ Wq,
    const int* __restrict__ mask, const float* __restrict__ wo)
{
    const int role = blockIdx.y;
    const int tid = threadIdx.x;

    if (role == 3) {
        #pragma unroll
        for (int it = 0; it < 8; it++) {
            size_t base = (((size_t)blockIdx.x * 8 + it) * 256 + tid) * 4;
            int4 v = *reinterpret_cast<const int4*>(mask + base);
            uint32_t nib = (uint32_t)(v.x != 0) | ((uint32_t)(v.y != 0) << 1)
                         | ((uint32_t)(v.z != 0) << 2) | ((uint32_t)(v.w != 0) << 3);
            nib |= __shfl_xor_sync(0xffffffffu, nib, 1) << 4;
            nib |= __shfl_xor_sync(0xffffffffu, nib, 2) << 8;
            nib |= __shfl_xor_sync(0xffffffffu, nib, 4) << 16;
            if ((tid & 7) == 0) g_mb[base >> 5] = nib;
        }
        return;
    }
    if (role == 4) {
        size_t i = ((size_t)blockIdx.x * 256 + tid) * 4;
        float4 f = *reinterpret_cast<const float4*>(wo + i);
        uint32_t u0 = packh2(f.x, f.y), u1 = packh2(f.z, f.w);
        *reinterpret_cast<uint2*>(g_wo + i) = make_uint2(u0, u1);
        return;
    }

    // ---- proj role (which = role 0..2) ----
    extern __shared__ char smc[];
    const uint32_t sb = smem_u32(smc);
    const uint32_t AS = sb, WS = sb + 16384;

    const int which = role;
    const float* in = (which == 0) ? vin : (which == 1) ? kin : qin;
    const float* W  = (which == 0) ? Wv  : (which == 1) ? Wk  : Wq;
    __half* outp    = (which == 0) ? g_v : (which == 1) ? g_k : g_q;
    const float wscale = (which == 2) ? XSCALE : 1.0f;

    const int m0 = blockIdx.x * 128;
    const int w = tid >> 5, L = tid & 31;

    for (int c = tid; c < 1024; c += 256) {
        int r = c >> 3, c0 = (c & 7) * 8;
        const float4* s = reinterpret_cast<const float4*>(in + (size_t)(m0 + r) * 64 + c0);
        float4 f0 = s[0], f1 = s[1];
        uint32_t u0 = packh2(f0.x, f0.y), u1 = packh2(f0.z, f0.w);
        uint32_t u2 = packh2(f1.x, f1.y), u3 = packh2(f1.z, f1.w);
        *reinterpret_cast<uint4*>(smc + SWZ(r * 128 + c0 * 2)) = make_uint4(u0, u1, u2, u3);
    }
    for (int c = tid; c < 512; c += 256) {
        int r = c >> 3, c0 = (c & 7) * 8;
        const float4* s = reinterpret_cast<const float4*>(W + (size_t)r * 64 + c0);
        float4 f0 = s[0], f1 = s[1];
        uint32_t u0 = packh2(f0.x * wscale, f0.y * wscale);
        uint32_t u1 = packh2(f0.z * wscale, f0.w * wscale);
        uint32_t u2 = packh2(f1.x * wscale, f1.y * wscale);
        uint32_t u3 = packh2(f1.z * wscale, f1.w * wscale);
        *reinterpret_cast<uint4*>(smc + 16384 + SWZ(r * 128 + c0 * 2)) = make_uint4(u0, u1, u2, u3);
    }
    __syncthreads();

    float acc[8][4] = {};
    const int lr = (L & 7) + ((L >> 3) & 1) * 8;
    const int lc = ((L >> 4) & 1) * 16;
    const int br = ((L >> 4) & 1) * 8 + (L & 7);
    const int bc = ((L >> 3) & 1) * 16;

    #pragma unroll
    for (int ks = 0; ks < 4; ks++) {
        uint32_t a[4];
        ldsm4(a, AS + SWZ((w * 16 + lr) * 128 + ks * 32 + lc));
        #pragma unroll
        for (int p = 0; p < 4; p++) {
            uint32_t b[4];
            ldsm4(b, WS + SWZ((p * 16 + br) * 128 + ks * 32 + bc));
            mma16816(acc[2*p],   a, &b[0]);
            mma16816(acc[2*p+1], a, &b[2]);
        }
    }

    // epilogue: stage packed fp16 into AS (reuse), then coalesced STG.128
    const int t4 = L >> 2, t2 = (L & 3) * 2;
    __syncthreads();   // all ldsm reads of AS/WS complete
    {
        const int row0 = w * 16 + t4, row1 = row0 + 8;
        #pragma unroll
        for (int f = 0; f < 8; f++) {
            int colb = (f * 8 + t2) * 2;
            uint32_t u0 = packh2(acc[f][0], acc[f][1]);
            uint32_t u1 = packh2(acc[f][2], acc[f][3]);
            *reinterpret_cast<uint32_t*>(smc + SWZ(row0 * 128 + colb)) = u0;
            *reinterpret_cast<uint32_t*>(smc + SWZ(row1 * 128 + colb)) = u1;
        }
    }
    __syncthreads();
    {
        const int rr = tid >> 1, hh = tid & 1;
        const int m = m0 + rr;
        const int hi = m & 15, li = (m >> 4) & 1023, ni = m >> 14;
        size_t base = ((size_t)((ni * 16 + hi) * 1024 + li)) * 64 + hh * 32;
        #pragma unroll
        for (int j = 0; j < 4; j++) {
            uint4 v = *reinterpret_cast<uint4*>(smc + SWZ(rr * 128 + hh * 64 + j * 16));
            *reinterpret_cast<uint4*>(outp + base + j * 8) = v;
        }
    }
}

// ---------------------------------------------------------------------------
// Flash attention: block = (128 q rows, head, batch); 8 warps x 16 rows.
// K-tiles of 64. 3-buffer cp.async ring, ONE barrier per tile (prefetch for
// kt+2 issued AFTER the barrier -> targets buf (kt-1)%3 which all warps have
// finished). MMA/softmax structure identical to R9 (known-good).
// smem: Q 16K | ring 3 x {K 8K, V 8K} = 64K
// ---------------------------------------------------------------------------
#define ATTN_SMEM 65536

__global__ __launch_bounds__(256, 2) void attn_mma()
{
    extern __shared__ char smc[];
    const uint32_t sb = smem_u32(smc);
    const uint32_t QS = sb;
    const uint32_t RING = sb + 16384;

    const int q0 = blockIdx.x * 128;
    const int h  = blockIdx.y;
    const int n  = blockIdx.z;
    const int tid = threadIdx.x;
    const int w = tid >> 5, L = tid & 31;

    const size_t head = (size_t)(n * NH + h) * SEQL * 64;
    const __half* qp = g_q + head;
    const __half* kp = g_k + head;
    const __half* vp = g_v + head;

    // prologue: group0 = Q + tile0 -> buf0; group1 = tile1 -> buf1
    for (int c = tid; c < 1024; c += 256) {
        int r = c >> 3, cb = (c & 7) * 16;
        CPA16(QS + SWZ(r * 128 + cb), (const char*)(qp + (size_t)(q0 + r) * 64) + cb);
    }
    for (int c = tid; c < 512; c += 256) {
        int r = c >> 3, cb = (c & 7) * 16;
        uint32_t off = SWZ(r * 128 + cb);
        size_t go = (size_t)r * 64;
        CPA16(RING + off,        (const char*)(kp + go) + cb);
        CPA16(RING + 8192 + off, (const char*)(vp + go) + cb);
    }
    CPC();
    for (int c = tid; c < 512; c += 256) {
        int r = c >> 3, cb = (c & 7) * 16;
        uint32_t off = SWZ(r * 128 + cb);
        size_t go = (size_t)(64 + r) * 64;
        CPA16(RING + 16384 + off,        (const char*)(kp + go) + cb);
        CPA16(RING + 16384 + 8192 + off, (const char*)(vp + go) + cb);
    }
    CPC();

    float o[8][4] = {};
    float lacc[4] = {};
    uint32_t aq[4][4];
    const uint32_t ones_b[2] = { 0x3C003C00u, 0x3C003C00u };

    const int lr = (L & 7) + ((L >> 3) & 1) * 8;
    const int lc = ((L >> 4) & 1) * 16;
    const int brr = ((L >> 4) & 1) * 8 + (L & 7);
    const int bcc = ((L >> 3) & 1) * 16;
    const int t4 = L >> 2, t2 = (L & 3) * 2;
    const int qa = q0 + w * 16 + t4, qb = qa + 8;

    const unsigned* mrow_a = g_mb + ((size_t)(n * SEQL + qa)) * 32;
    const unsigned* mrow_b = g_mb + ((size_t)(n * SEQL + qb)) * 32;

    int cur = 0, pre = 2;   // kt%3, (kt+2)%3
    for (int kt = 0; kt < 16; kt++) {
        // group kt must be complete (pending: kt, kt+1)
        if (kt < 15) { CPW1(); } else { CPW0(); }
        __syncthreads();   // single barrier: kt data visible AND kt-1 reads done

        // prefetch kt+2 into buf (kt+2)%3 == (kt-1)%3 (safe after barrier)
        if (kt < 14) {
            uint32_t B = RING + pre * 16384;
            const int k0 = (kt + 2) * 64;
            for (int c = tid; c < 512; c += 256) {
                int r = c >> 3, cb = (c & 7) * 16;
                uint32_t off = SWZ(r * 128 + cb);
                size_t go = (size_t)(k0 + r) * 64;
                CPA16(B + off,        (const char*)(kp + go) + cb);
                CPA16(B + 8192 + off, (const char*)(vp + go) + cb);
            }
            CPC();
        }

        // prefetch mask words (LDG overlaps S-MMA block)
        unsigned wa0 = mrow_a[kt * 2], wa1 = mrow_a[kt * 2 + 1];
        unsigned wb0 = mrow_b[kt * 2], wb1 = mrow_b[kt * 2 + 1];

        if (kt == 0) {
            #pragma unroll
            for (int ks = 0; ks < 4; ks++)
                ldsm4(aq[ks], QS + SWZ((w * 16 + lr) * 128 + ks * 32 + lc));
        }

        const uint32_t KB = RING + cur * 16384;
        const uint32_t VB = KB + 8192;

        // S = Q K^T  (already log2-scaled)
        float s[8][4] = {};
        #pragma unroll
        for (int ks = 0; ks < 4; ks++) {
            #pragma unroll
            for (int p = 0; p < 4; p++) {
                uint32_t bh[4];
                ldsm4(bh, KB + SWZ((p * 16 + brr) * 128 + ks * 32 + bcc));
                mma16816(s[2*p],   aq[ks], &bh[0]);
                mma16816(s[2*p+1], aq[ks], &bh[2]);
            }
        }

        // mask-select -> pack -> ex2 (straight-line)
        uint32_t preg[8][2];
        #pragma unroll
        for (int f = 0; f < 8; f++) {
            unsigned wA = (f < 4) ? wa0 : wa1;
            unsigned wB = (f < 4) ? wb0 : wb1;
            int bit = (f & 3) * 8 + t2;
            float xa0 = ((wA >> bit) & 1)       ? s[f][0] : -100.f;
            float xa1 = ((wA >> (bit + 1)) & 1) ? s[f][1] : -100.f;
            float xb0 = ((wB >> bit) & 1)       ? s[f][2] : -100.f;
            float xb1 = ((wB >> (bit + 1)) & 1) ? s[f][3] : -100.f;
            preg[f][0] = h2ex2(packh2(xa0, xa1));
            preg[f][1] = h2ex2(packh2(xb0, xb1));
        }

        // O += P V ; l += P @ ones
        #pragma unroll
        for (int ks = 0; ks < 4; ks++) {
            uint32_t ph[4] = { preg[2*ks][0], preg[2*ks][1],
                               preg[2*ks+1][0], preg[2*ks+1][1] };
            mma16816(lacc, ph, ones_b);
            #pragma unroll
            for (int p = 0; p < 4; p++) {
                uint32_t bh[4];
                ldsm4t(bh, VB + SWZ((ks * 16 + lr) * 128 + p * 32 + lc));
                mma16816(o[2*p],   ph, &bh[0]);
                mma16816(o[2*p+1], ph, &bh[2]);
            }
        }

        cur = (cur == 2) ? 0 : cur + 1;
        pre = (pre == 2) ? 0 : pre + 1;
    }

    // epilogue: l complete per row; normalize, store
    float ia = 1.0f / lacc[0], ib = 1.0f / lacc[2];
    size_t ba = ((size_t)(n * SEQL + qa)) * EMB + h * 64;
    size_t bb = ((size_t)(n * SEQL + qb)) * EMB + h * 64;
    #pragma unroll
    for (int f = 0; f < 8; f++) {
        int col = f * 8 + t2;
        *reinterpret_cast<uint32_t*>(g_ao + ba + col) = packh2(o[f][0] * ia, o[f][1] * ia);
        *reinterpret_cast<uint32_t*>(g_ao + bb + col) = packh2(o[f][2] * ib, o[f][3] * ib);
    }
}

// ---------------------------------------------------------------------------
// Output projection: (8192 x 1024) @ (1024 x 1024)^T + bias, pure fp16 1-term.
// Tile 128x128, 256 threads, K chunks of 64. 3-buffer cp.async ring, ONE
// barrier per tile. smem: 3 x {A 16K | B 16K} = 96K; 2 CTAs/SM (192K < 227K).
// ---------------------------------------------------------------------------
#define OUT_SMEM 98304

__global__ __launch_bounds__(256, 2) void outproj_mma(
    const float* __restrict__ bo, float* __restrict__ out)
{
    extern __shared__ char smc[];
    const uint32_t sb = smem_u32(smc);

    const int m0 = blockIdx.x * 128;
    const int e0 = blockIdx.y * 128;
    const int tid = threadIdx.x;
    const int w = tid >> 5, L = tid & 31;

    // prologue: chunks 0 and 1 -> bufs 0, 1
    #pragma unroll
    for (int pk = 0; pk < 2; pk++) {
        uint32_t B = sb + pk * 32768;
        const int k0 = pk * 64;
        for (int c = tid; c < 1024; c += 256) {
            int r = c >> 3, cb = (c & 7) * 16;
            uint32_t off = SWZ(r * 128 + cb);
            CPA16(B + off,         (const char*)(g_ao + (size_t)(m0 + r) * EMB + k0) + cb);
            CPA16(B + 16384 + off, (const char*)(g_wo + (size_t)(e0 + r) * EMB + k0) + cb);
        }
        CPC();
    }

    float acc[16][4] = {};
    const int lr = (L & 7) + ((L >> 3) & 1) * 8;
    const int lc = ((L >> 4) & 1) * 16;
    const int brr = ((L >> 4) & 1) * 8 + (L & 7);
    const int bcc = ((L >> 3) & 1) * 16;

    int cur = 0, pre = 2;
    for (int kt = 0; kt < 16; kt++) {
        if (kt < 15) { CPW1(); } else { CPW0(); }
        __syncthreads();

        if (kt < 14) {
            uint32_t B = sb + pre * 32768;
            const int k0 = (kt + 2) * 64;
            for (int c = tid; c < 1024; c += 256) {
                int r = c >> 3, cb = (c & 7) * 16;
                uint32_t off = SWZ(r * 128 + cb);
                CPA16(B + off,         (const char*)(g_ao + (size_t)(m0 + r) * EMB + k0) + cb);
                CPA16(B + 16384 + off, (const char*)(g_wo + (size_t)(e0 + r) * EMB + k0) + cb);
            }
            CPC();
        }

        const uint32_t AS = sb + cur * 32768;
        const uint32_t BS = AS + 16384;

        #pragma unroll
        for (int ks = 0; ks < 4; ks++) {
            uint32_t a[4];
            ldsm4(a, AS + SWZ((w * 16 + lr) * 128 + ks * 32 + lc));
            #pragma unroll
            for (int p = 0; p < 8; p++) {
                uint32_t b[4];
                ldsm4(b, BS + SWZ((p * 16 + brr) * 128 + ks * 32 + bcc));
                mma16816(acc[2*p],   a, &b[0]);
                mma16816(acc[2*p+1], a, &b[2]);
            }
        }

        cur = (cur == 2) ? 0 : cur + 1;
        pre = (pre == 2) ? 0 : pre + 1;
    }

    // epilogue
    const int t4 = L >> 2, t2 = (L & 3) * 2;
    const int r0 = m0 + w * 16 + t4, r1 = r0 + 8;
    #pragma unroll
    for (int f = 0; f < 16; f++) {
        int col = e0 + f * 8 + t2;
        float b0v = bo[col], b1v = bo[col + 1];
        float2 v0 = make_float2(acc[f][0] + b0v, acc[f][1] + b1v);
        float2 v1 = make_float2(acc[f][2] + b0v, acc[f][3] + b1v);
        *reinterpret_cast<float2*>(out + (size_t)r0 * EMB + col) = v0;
        *reinterpret_cast<float2*>(out + (size_t)r1 * EMB + col) = v1;
    }
}

// ---------------------------------------------------------------------------
extern "C" void kernel_launch(void* const* d_in, const int* in_sizes, int n_in,
                              void* d_out, int out_size)
{
    const float* values = (const float*)d_in[0];
    const float* keys   = (const float*)d_in[1];
    const float* query  = (const float*)d_in[2];
    const int*   mask   = (const int*)d_in[3];
    const float* Wv     = (const float*)d_in[4];
    const float* Wk     = (const float*)d_in[5];
    const float* Wq     = (const float*)d_in[6];
    const float* Wo     = (const float*)d_in[7];
    const float* bo     = (const float*)d_in[8];
    float* out = (float*)d_out;
    (void)in_sizes; (void)n_in; (void)out_size;

    cudaFuncSetAttribute(front_kernel, cudaFuncAttributeMaxDynamicSharedMemorySize, FRONT_SMEM);
    cudaFuncSetAttribute(attn_mma,     cudaFuncAttributeMaxDynamicSharedMemorySize, ATTN_SMEM);
    cudaFuncSetAttribute(outproj_mma,  cudaFuncAttributeMaxDynamicSharedMemorySize, OUT_SMEM);

    front_kernel<<<dim3(1024, 5), 256, FRONT_SMEM>>>(values, keys, query,
                                                     Wv, Wk, Wq, mask, Wo);
    attn_mma<<<dim3(SEQL/128, NH, NB), 256, ATTN_SMEM>>>();
    outproj_mma<<<dim3(64, 8), 256, OUT_SMEM>>>(bo, out);
}

// round 17
// speedup vs baseline: 1.5074x; 1.0192x over previous
#include <cuda_runtime.h>
#include <cuda_fp16.h>
#include <cstdint>
#include <float.h>

#define NB   8
#define SEQL 1024
#define NH   16
#define HD   64
#define EMB  1024

// ---------------------------------------------------------------------------
// Device scratch (allocation-free rule)
// ---------------------------------------------------------------------------
__device__ __half g_q [NB*NH*SEQL*HD];     // projected Q (fp16, pre-scaled by XSCALE)
__device__ __half g_k [NB*NH*SEQL*HD];     // projected K (fp16)
__device__ __half g_v [NB*NH*SEQL*HD];     // projected V (fp16)
__device__ __half g_ao[NB*SEQL*EMB];       // attention out (fp16) [n][l][e]
__device__ __half g_wo[EMB*EMB];           // Wo fp16
__device__ unsigned g_mb[NB*SEQL*SEQL/32]; // packed mask bits

// log2 domain: softmax(z/32) = exp2(z * C) / sum, C = log2(e)/32, folded into Wq.
#define XSCALE 0.0450842139f          /* 0.03125 * log2(e) */

// ---------------------------------------------------------------------------
// helpers
// ---------------------------------------------------------------------------
__device__ __forceinline__ uint32_t smem_u32(const void* p) {
    uint32_t a;
    asm("{ .reg .u64 t; cvta.to.shared.u64 t, %1; cvt.u32.u64 %0, t; }"
        : "=r"(a) : "l"(p));
    return a;
}

#define SWZ(o) ((o) ^ ((((uint32_t)(o)) >> 3) & 0x70u))

__device__ __forceinline__ void ldsm4(uint32_t r[4], uint32_t a) {
    asm volatile("ldmatrix.sync.aligned.m8n8.x4.shared.b16 {%0,%1,%2,%3}, [%4];"
        : "=r"(r[0]), "=r"(r[1]), "=r"(r[2]), "=r"(r[3]) : "r"(a));
}
__device__ __forceinline__ void ldsm4t(uint32_t r[4], uint32_t a) {
    asm volatile("ldmatrix.sync.aligned.m8n8.x4.trans.shared.b16 {%0,%1,%2,%3}, [%4];"
        : "=r"(r[0]), "=r"(r[1]), "=r"(r[2]), "=r"(r[3]) : "r"(a));
}
__device__ __forceinline__ void mma16816(float* c, const uint32_t* a, const uint32_t* b) {
    asm volatile("mma.sync.aligned.m16n8k16.row.col.f32.f16.f16.f32 "
        "{%0,%1,%2,%3}, {%4,%5,%6,%7}, {%8,%9}, {%0,%1,%2,%3};"
        : "+f"(c[0]), "+f"(c[1]), "+f"(c[2]), "+f"(c[3])
        : "r"(a[0]), "r"(a[1]), "r"(a[2]), "r"(a[3]), "r"(b[0]), "r"(b[1]));
}
__device__ __forceinline__ uint32_t h2ex2(uint32_t x) {
    uint32_t r;
    asm("ex2.approx.f16x2 %0, %1;" : "=r"(r) : "r"(x));
    return r;
}
__device__ __forceinline__ uint32_t packh2(float a, float b) {
    __half2 h = __floats2half2_rn(a, b);
    return *reinterpret_cast<uint32_t*>(&h);
}

#define CPA16(dst, src) \
    asm volatile("cp.async.cg.shared.global [%0], [%1], 16;" \
        :: "r"((uint32_t)(dst)), "l"((const void*)(src)) : "memory")
#define CPC()  asm volatile("cp.async.commit_group;" ::: "memory")
#define CPW0() asm volatile("cp.async.wait_group 0;" ::: "memory")
#define CPW1() asm volatile("cp.async.wait_group 1;" ::: "memory")

// ---------------------------------------------------------------------------
// Fused front kernel: grid (1024, 5), 256 threads.
//   y = 0..2 : QKV projection (pure fp16 MMA), which = y
//   y = 3    : mask bit-packing (8 chunks per block)
//   y = 4    : Wo fp32 -> fp16 conversion
// R17: every role split into load-phase (all LDGs batched, MLP ~8) then
// convert/store-phase, to raise DRAM latency overlap.
// smem (proj role): A 16K | W 8K = 24K
// ---------------------------------------------------------------------------
#define FRONT_SMEM 24576

__global__ __launch_bounds__(256) void front_kernel(
    const float* __restrict__ vin, const float* __restrict__ kin,
    const float* __restrict__ qin,
    const float* __restrict__ Wv, const float* __restrict__ Wk,
    const float* __restrict__ Wq,
    const int* __restrict__ mask, const float* __restrict__ wo)
{
    const int role = blockIdx.y;
    const int tid = threadIdx.x;

    if (role == 3) {
        // load phase: 8 independent int4 LDGs in flight
        int4 vb[8];
        #pragma unroll
        for (int it = 0; it < 8; it++) {
            size_t base = (((size_t)blockIdx.x * 8 + it) * 256 + tid) * 4;
            vb[it] = *reinterpret_cast<const int4*>(mask + base);
        }
        // process/store phase
        #pragma unroll
        for (int it = 0; it < 8; it++) {
            size_t base = (((size_t)blockIdx.x * 8 + it) * 256 + tid) * 4;
            int4 v = vb[it];
            uint32_t nib = (uint32_t)(v.x != 0) | ((uint32_t)(v.y != 0) << 1)
                         | ((uint32_t)(v.z != 0) << 2) | ((uint32_t)(v.w != 0) << 3);
            nib |= __shfl_xor_sync(0xffffffffu, nib, 1) << 4;
            nib |= __shfl_xor_sync(0xffffffffu, nib, 2) << 8;
            nib |= __shfl_xor_sync(0xffffffffu, nib, 4) << 16;
            if ((tid & 7) == 0) g_mb[base >> 5] = nib;
        }
        return;
    }
    if (role == 4) {
        size_t i = ((size_t)blockIdx.x * 256 + tid) * 4;
        float4 f = *reinterpret_cast<const float4*>(wo + i);
        uint32_t u0 = packh2(f.x, f.y), u1 = packh2(f.z, f.w);
        *reinterpret_cast<uint2*>(g_wo + i) = make_uint2(u0, u1);
        return;
    }

    // ---- proj role (which = role 0..2) ----
    extern __shared__ char smc[];
    const uint32_t sb = smem_u32(smc);
    const uint32_t AS = sb, WS = sb + 16384;

    const int which = role;
    const float* in = (which == 0) ? vin : (which == 1) ? kin : qin;
    const float* W  = (which == 0) ? Wv  : (which == 1) ? Wk  : Wq;
    __half* outp    = (which == 0) ? g_v : (which == 1) ? g_k : g_q;
    const float wscale = (which == 2) ? XSCALE : 1.0f;

    const int m0 = blockIdx.x * 128;
    const int w = tid >> 5, L = tid & 31;

    // load phase: A (8 float4) + W (4 float4), all LDGs issued before any use
    float4 fa[8], fw[4];
    #pragma unroll
    for (int it = 0; it < 4; it++) {
        int c = tid + it * 256;
        int r = c >> 3, c0 = (c & 7) * 8;
        const float4* s = reinterpret_cast<const float4*>(in + (size_t)(m0 + r) * 64 + c0);
        fa[2 * it]     = s[0];
        fa[2 * it + 1] = s[1];
    }
    #pragma unroll
    for (int it = 0; it < 2; it++) {
        int c = tid + it * 256;
        int r = c >> 3, c0 = (c & 7) * 8;
        const float4* s = reinterpret_cast<const float4*>(W + (size_t)r * 64 + c0);
        fw[2 * it]     = s[0];
        fw[2 * it + 1] = s[1];
    }

    // convert/store phase
    #pragma unroll
    for (int it = 0; it < 4; it++) {
        int c = tid + it * 256;
        int r = c >> 3, c0 = (c & 7) * 8;
        float4 f0 = fa[2 * it], f1 = fa[2 * it + 1];
        uint32_t u0 = packh2(f0.x, f0.y), u1 = packh2(f0.z, f0.w);
        uint32_t u2 = packh2(f1.x, f1.y), u3 = packh2(f1.z, f1.w);
        *reinterpret_cast<uint4*>(smc + SWZ(r * 128 + c0 * 2)) = make_uint4(u0, u1, u2, u3);
    }
    #pragma unroll
    for (int it = 0; it < 2; it++) {
        int c = tid + it * 256;
        int r = c >> 3, c0 = (c & 7) * 8;
        float4 f0 = fw[2 * it], f1 = fw[2 * it + 1];
        uint32_t u0 = packh2(f0.x * wscale, f0.y * wscale);
        uint32_t u1 = packh2(f0.z * wscale, f0.w * wscale);
        uint32_t u2 = packh2(f1.x * wscale, f1.y * wscale);
        uint32_t u3 = packh2(f1.z * wscale, f1.w * wscale);
        *reinterpret_cast<uint4*>(smc + 16384 + SWZ(r * 128 + c0 * 2)) = make_uint4(u0, u1, u2, u3);
    }
    __syncthreads();

    float acc[8][4] = {};
    const int lr = (L & 7) + ((L >> 3) & 1) * 8;
    const int lc = ((L >> 4) & 1) * 16;
    const int br = ((L >> 4) & 1) * 8 + (L & 7);
    const int bc = ((L >> 3) & 1) * 16;

    #pragma unroll
    for (int ks = 0; ks < 4; ks++) {
        uint32_t a[4];
        ldsm4(a, AS + SWZ((w * 16 + lr) * 128 + ks * 32 + lc));
        #pragma unroll
        for (int p = 0; p < 4; p++) {
            uint32_t b[4];
            ldsm4(b, WS + SWZ((p * 16 + br) * 128 + ks * 32 + bc));
            mma16816(acc[2*p],   a, &b[0]);
            mma16816(acc[2*p+1], a, &b[2]);
        }
    }

    // epilogue: stage packed fp16 into AS (reuse), then coalesced STG.128
    const int t4 = L >> 2, t2 = (L & 3) * 2;
    __syncthreads();   // all ldsm reads of AS/WS complete
    {
        const int row0 = w * 16 + t4, row1 = row0 + 8;
        #pragma unroll
        for (int f = 0; f < 8; f++) {
            int colb = (f * 8 + t2) * 2;
            uint32_t u0 = packh2(acc[f][0], acc[f][1]);
            uint32_t u1 = packh2(acc[f][2], acc[f][3]);
            *reinterpret_cast<uint32_t*>(smc + SWZ(row0 * 128 + colb)) = u0;
            *reinterpret_cast<uint32_t*>(smc + SWZ(row1 * 128 + colb)) = u1;
        }
    }
    __syncthreads();
    {
        const int rr = tid >> 1, hh = tid & 1;
        const int m = m0 + rr;
        const int hi = m & 15, li = (m >> 4) & 1023, ni = m >> 14;
        size_t base = ((size_t)((ni * 16 + hi) * 1024 + li)) * 64 + hh * 32;
        #pragma unroll
        for (int j = 0; j < 4; j++) {
            uint4 v = *reinterpret_cast<uint4*>(smc + SWZ(rr * 128 + hh * 64 + j * 16));
            *reinterpret_cast<uint4*>(outp + base + j * 8) = v;
        }
    }
}

// ---------------------------------------------------------------------------
// Flash attention (byte-identical to validated 215.5us config): block =
// (128 q rows, head, batch); 8 warps x 16 rows. K-tiles of 64. 3-buffer
// cp.async ring, ONE barrier per tile. No-max log2 softmax; l = P @ ones.
// smem: Q 16K | ring 3 x {K 8K, V 8K} = 64K; 2 CTAs/SM.
// ---------------------------------------------------------------------------
#define ATTN_SMEM 65536

__global__ __launch_bounds__(256, 2) void attn_mma()
{
    extern __shared__ char smc[];
    const uint32_t sb = smem_u32(smc);
    const uint32_t QS = sb;
    const uint32_t RING = sb + 16384;

    const int q0 = blockIdx.x * 128;
    const int h  = blockIdx.y;
    const int n  = blockIdx.z;
    const int tid = threadIdx.x;
    const int w = tid >> 5, L = tid & 31;

    const size_t head = (size_t)(n * NH + h) * SEQL * 64;
    const __half* qp = g_q + head;
    const __half* kp = g_k + head;
    const __half* vp = g_v + head;

    // prologue: group0 = Q + tile0 -> buf0; group1 = tile1 -> buf1
    for (int c = tid; c < 1024; c += 256) {
        int r = c >> 3, cb = (c & 7) * 16;
        CPA16(QS + SWZ(r * 128 + cb), (const char*)(qp + (size_t)(q0 + r) * 64) + cb);
    }
    for (int c = tid; c < 512; c += 256) {
        int r = c >> 3, cb = (c & 7) * 16;
        uint32_t off = SWZ(r * 128 + cb);
        size_t go = (size_t)r * 64;
        CPA16(RING + off,        (const char*)(kp + go) + cb);
        CPA16(RING + 8192 + off, (const char*)(vp + go) + cb);
    }
    CPC();
    for (int c = tid; c < 512; c += 256) {
        int r = c >> 3, cb = (c & 7) * 16;
        uint32_t off = SWZ(r * 128 + cb);
        size_t go = (size_t)(64 + r) * 64;
        CPA16(RING + 16384 + off,        (const char*)(kp + go) + cb);
        CPA16(RING + 16384 + 8192 + off, (const char*)(vp + go) + cb);
    }
    CPC();

    float o[8][4] = {};
    float lacc[4] = {};
    uint32_t aq[4][4];
    const uint32_t ones_b[2] = { 0x3C003C00u, 0x3C003C00u };

    const int lr = (L & 7) + ((L >> 3) & 1) * 8;
    const int lc = ((L >> 4) & 1) * 16;
    const int brr = ((L >> 4) & 1) * 8 + (L & 7);
    const int bcc = ((L >> 3) & 1) * 16;
    const int t4 = L >> 2, t2 = (L & 3) * 2;
    const int qa = q0 + w * 16 + t4, qb = qa + 8;

    const unsigned* mrow_a = g_mb + ((size_t)(n * SEQL + qa)) * 32;
    const unsigned* mrow_b = g_mb + ((size_t)(n * SEQL + qb)) * 32;

    int cur = 0, pre = 2;   // kt%3, (kt+2)%3
    for (int kt = 0; kt < 16; kt++) {
        // group kt must be complete (pending: kt, kt+1)
        if (kt < 15) { CPW1(); } else { CPW0(); }
        __syncthreads();   // single barrier: kt data visible AND kt-1 reads done

        // prefetch kt+2 into buf (kt+2)%3 == (kt-1)%3 (safe after barrier)
        if (kt < 14) {
            uint32_t B = RING + pre * 16384;
            const int k0 = (kt + 2) * 64;
            for (int c = tid; c < 512; c += 256) {
                int r = c >> 3, cb = (c & 7) * 16;
                uint32_t off = SWZ(r * 128 + cb);
                size_t go = (size_t)(k0 + r) * 64;
                CPA16(B + off,        (const char*)(kp + go) + cb);
                CPA16(B + 8192 + off, (const char*)(vp + go) + cb);
            }
            CPC();
        }

        // prefetch mask words (LDG overlaps S-MMA block)
        unsigned wa0 = mrow_a[kt * 2], wa1 = mrow_a[kt * 2 + 1];
        unsigned wb0 = mrow_b[kt * 2], wb1 = mrow_b[kt * 2 + 1];

        if (kt == 0) {
            #pragma unroll
            for (int ks = 0; ks < 4; ks++)
                ldsm4(aq[ks], QS + SWZ((w * 16 + lr) * 128 + ks * 32 + lc));
        }

        const uint32_t KB = RING + cur * 16384;
        const uint32_t VB = KB + 8192;

        // S = Q K^T  (already log2-scaled)
        float s[8][4] = {};
        #pragma unroll
        for (int ks = 0; ks < 4; ks++) {
            #pragma unroll
            for (int p = 0; p < 4; p++) {
                uint32_t bh[4];
                ldsm4(bh, KB + SWZ((p * 16 + brr) * 128 + ks * 32 + bcc));
                mma16816(s[2*p],   aq[ks], &bh[0]);
                mma16816(s[2*p+1], aq[ks], &bh[2]);
            }
        }

        // mask-select -> pack -> ex2 (straight-line)
        uint32_t preg[8][2];
        #pragma unroll
        for (int f = 0; f < 8; f++) {
            unsigned wA = (f < 4) ? wa0 : wa1;
            unsigned wB = (f < 4) ? wb0 : wb1;
            int bit = (f & 3) * 8 + t2;
            float xa0 = ((wA >> bit) & 1)       ? s[f][0] : -100.f;
            float xa1 = ((wA >> (bit + 1)) & 1) ? s[f][1] : -100.f;
            float xb0 = ((wB >> bit) & 1)       ? s[f][2] : -100.f;
            float xb1 = ((wB >> (bit + 1)) & 1) ? s[f][3] : -100.f;
            preg[f][0] = h2ex2(packh2(xa0, xa1));
            preg[f][1] = h2ex2(packh2(xb0, xb1));
        }

        // O += P V ; l += P @ ones
        #pragma unroll
        for (int ks = 0; ks < 4; ks++) {
            uint32_t ph[4] = { preg[2*ks][0], preg[2*ks][1],
                               preg[2*ks+1][0], preg[2*ks+1][1] };
            mma16816(lacc, ph, ones_b);
            #pragma unroll
            for (int p = 0; p < 4; p++) {
                uint32_t bh[4];
                ldsm4t(bh, VB + SWZ((ks * 16 + lr) * 128 + p * 32 + lc));
                mma16816(o[2*p],   ph, &bh[0]);
                mma16816(o[2*p+1], ph, &bh[2]);
            }
        }

        cur = (cur == 2) ? 0 : cur + 1;
        pre = (pre == 2) ? 0 : pre + 1;
    }

    // epilogue: l complete per row; normalize, store
    float ia = 1.0f / lacc[0], ib = 1.0f / lacc[2];
    size_t ba = ((size_t)(n * SEQL + qa)) * EMB + h * 64;
    size_t bb = ((size_t)(n * SEQL + qb)) * EMB + h * 64;
    #pragma unroll
    for (int f = 0; f < 8; f++) {
        int col = f * 8 + t2;
        *reinterpret_cast<uint32_t*>(g_ao + ba + col) = packh2(o[f][0] * ia, o[f][1] * ia);
        *reinterpret_cast<uint32_t*>(g_ao + bb + col) = packh2(o[f][2] * ib, o[f][3] * ib);
    }
}

// ---------------------------------------------------------------------------
// Output projection (byte-identical to validated config): (8192 x 1024) @
// (1024 x 1024)^T + bias, pure fp16 1-term. Tile 128x128, 256 threads,
// K chunks of 64. 3-buffer cp.async ring, ONE barrier per tile.
// smem: 3 x {A 16K | B 16K} = 96K; 2 CTAs/SM.
// ---------------------------------------------------------------------------
#define OUT_SMEM 98304

__global__ __launch_bounds__(256, 2) void outproj_mma(
    const float* __restrict__ bo, float* __restrict__ out)
{
    extern __shared__ char smc[];
    const uint32_t sb = smem_u32(smc);

    const int m0 = blockIdx.x * 128;
    const int e0 = blockIdx.y * 128;
    const int tid = threadIdx.x;
    const int w = tid >> 5, L = tid & 31;

    // prologue: chunks 0 and 1 -> bufs 0, 1
    #pragma unroll
    for (int pk = 0; pk < 2; pk++) {
        uint32_t B = sb + pk * 32768;
        const int k0 = pk * 64;
        for (int c = tid; c < 1024; c += 256) {
            int r = c >> 3, cb = (c & 7) * 16;
            uint32_t off = SWZ(r * 128 + cb);
            CPA16(B + off,         (const char*)(g_ao + (size_t)(m0 + r) * EMB + k0) + cb);
            CPA16(B + 16384 + off, (const char*)(g_wo + (size_t)(e0 + r) * EMB + k0) + cb);
        }
        CPC();
    }

    float acc[16][4] = {};
    const int lr = (L & 7) + ((L >> 3) & 1) * 8;
    const int lc = ((L >> 4) & 1) * 16;
    const int brr = ((L >> 4) & 1) * 8 + (L & 7);
    const int bcc = ((L >> 3) & 1) * 16;

    int cur = 0, pre = 2;
    for (int kt = 0; kt < 16; kt++) {
        if (kt < 15) { CPW1(); } else { CPW0(); }
        __syncthreads();

        if (kt < 14) {
            uint32_t B = sb + pre * 32768;
            const int k0 = (kt + 2) * 64;
            for (int c = tid; c < 1024; c += 256) {
                int r = c >> 3, cb = (c & 7) * 16;
                uint32_t off = SWZ(r * 128 + cb);
                CPA16(B + off,         (const char*)(g_ao + (size_t)(m0 + r) * EMB + k0) + cb);
                CPA16(B + 16384 + off, (const char*)(g_wo + (size_t)(e0 + r) * EMB + k0) + cb);
            }
            CPC();
        }

        const uint32_t AS = sb + cur * 32768;
        const uint32_t BS = AS + 16384;

        #pragma unroll
        for (int ks = 0; ks < 4; ks++) {
            uint32_t a[4];
            ldsm4(a, AS + SWZ((w * 16 + lr) * 128 + ks * 32 + lc));
            #pragma unroll
            for (int p = 0; p < 8; p++) {
                uint32_t b[4];
                ldsm4(b, BS + SWZ((p * 16 + brr) * 128 + ks * 32 + bcc));
                mma16816(acc[2*p],   a, &b[0]);
                mma16816(acc[2*p+1], a, &b[2]);
            }
        }

        cur = (cur == 2) ? 0 : cur + 1;
        pre = (pre == 2) ? 0 : pre + 1;
    }

    // epilogue
    const int t4 = L >> 2, t2 = (L & 3) * 2;
    const int r0 = m0 + w * 16 + t4, r1 = r0 + 8;
    #pragma unroll
    for (int f = 0; f < 16; f++) {
        int col = e0 + f * 8 + t2;
        float b0v = bo[col], b1v = bo[col + 1];
        float2 v0 = make_float2(acc[f][0] + b0v, acc[f][1] + b1v);
        float2 v1 = make_float2(acc[f][2] + b0v, acc[f][3] + b1v);
        *reinterpret_cast<float2*>(out + (size_t)r0 * EMB + col) = v0;
        *reinterpret_cast<float2*>(out + (size_t)r1 * EMB + col) = v1;
    }
}

// ---------------------------------------------------------------------------
extern "C" void kernel_launch(void* const* d_in, const int* in_sizes, int n_in,
                              void* d_out, int out_size)
{
    const float* values = (const float*)d_in[0];
    const float* keys   = (const float*)d_in[1];
    const float* query  = (const float*)d_in[2];
    const int*   mask   = (const int*)d_in[3];
    const float* Wv     = (const float*)d_in[4];
    const float* Wk     = (const float*)d_in[5];
    const float* Wq     = (const float*)d_in[6];
    const float* Wo     = (const float*)d_in[7];
    const float* bo     = (const float*)d_in[8];
    float* out = (float*)d_out;
    (void)in_sizes; (void)n_in; (void)out_size;

    cudaFuncSetAttribute(front_kernel, cudaFuncAttributeMaxDynamicSharedMemorySize, FRONT_SMEM);
    cudaFuncSetAttribute(attn_mma,     cudaFuncAttributeMaxDynamicSharedMemorySize, ATTN_SMEM);
    cudaFuncSetAttribute(outproj_mma,  cudaFuncAttributeMaxDynamicSharedMemorySize, OUT_SMEM);

    front_kernel<<<dim3(1024, 5), 256, FRONT_SMEM>>>(values, keys, query,
                                                     Wv, Wk, Wq, mask, Wo);
    attn_mma<<<dim3(SEQL/128, NH, NB), 256, ATTN_SMEM>>>();
    outproj_mma<<<dim3(64, 8), 256, OUT_SMEM>>>(bo, out);
}